// round 8
// baseline (speedup 1.0000x reference)
#include <cuda_runtime.h>
#include <cuda_bf16.h>
#include <cstdint>

// ---------------------------------------------------------------------------
// MultiLayerAttention: out = proj( softmax_causal( (hidden@Wq^T+bq) K^T / sqrt(D) ) V )
// B=2, S=2048, H=2048, 16 Q heads, 4 KV heads (G=4), D=128.
// R6: projections on tensor cores via mma.sync bf16 (hi/lo split, 3 MMAs),
//     since tcgen05 PTX is rejected at the harness's compute_103 target.
// ---------------------------------------------------------------------------

#define B_   2
#define S_   2048
#define H_   2048
#define NH_  16
#define NKV_ 4
#define D_   128

// Scratch (allocation-free rule: device globals)
static __device__ float g_q[(size_t)B_ * NH_ * S_ * D_];          // 32 MB
static __device__ float g_ctx[(size_t)B_ * S_ * H_];              // 32 MB
static __device__ __nv_bfloat16 g_aH[(size_t)B_ * S_ * H_];       // 16 MB
static __device__ __nv_bfloat16 g_aL[(size_t)B_ * S_ * H_];       // 16 MB
static __device__ __nv_bfloat16 g_wH[(size_t)H_ * H_];            // 8 MB
static __device__ __nv_bfloat16 g_wL[(size_t)H_ * H_];            // 8 MB

// ============================ MMA helpers ==================================
__device__ __forceinline__ uint32_t smem_u32(const void* p) {
    uint32_t a;
    asm("{ .reg .u64 t; cvta.to.shared.u64 t, %1; cvt.u32.u64 %0, t; }" : "=r"(a) : "l"(p));
    return a;
}
__device__ __forceinline__ void ldmat_x4(uint32_t* r, uint32_t addr) {
    asm volatile("ldmatrix.sync.aligned.m8n8.x4.shared.b16 {%0,%1,%2,%3}, [%4];"
                 : "=r"(r[0]), "=r"(r[1]), "=r"(r[2]), "=r"(r[3]) : "r"(addr));
}
__device__ __forceinline__ void mma_bf16(float* d, const uint32_t* a, const uint32_t* b) {
    asm volatile("mma.sync.aligned.m16n8k16.row.col.f32.bf16.bf16.f32 "
                 "{%0,%1,%2,%3}, {%4,%5,%6,%7}, {%8,%9}, {%0,%1,%2,%3};"
                 : "+f"(d[0]), "+f"(d[1]), "+f"(d[2]), "+f"(d[3])
                 : "r"(a[0]), "r"(a[1]), "r"(a[2]), "r"(a[3]), "r"(b[0]), "r"(b[1]));
}

// ---------------------------------------------------------------------------
// fp32 -> (bf16 hi, bf16 lo) split conversion
// ---------------------------------------------------------------------------
__global__ __launch_bounds__(256) void split_bf16_kernel(
    const float* __restrict__ src, __nv_bfloat16* __restrict__ hi,
    __nv_bfloat16* __restrict__ lo, int n4)
{
    int i = blockIdx.x * blockDim.x + threadIdx.x;
    if (i >= n4) return;
    float4 x = ((const float4*)src)[i];
    __nv_bfloat16 h0 = __float2bfloat16(x.x), h1 = __float2bfloat16(x.y);
    __nv_bfloat16 h2 = __float2bfloat16(x.z), h3 = __float2bfloat16(x.w);
    __nv_bfloat162 hh0{h0, h1}, hh1{h2, h3};
    __nv_bfloat162 ll0{__float2bfloat16(x.x - __bfloat162float(h0)),
                       __float2bfloat16(x.y - __bfloat162float(h1))};
    __nv_bfloat162 ll1{__float2bfloat16(x.z - __bfloat162float(h2)),
                       __float2bfloat16(x.w - __bfloat162float(h3))};
    ((__nv_bfloat162*)hi)[i * 2]     = hh0;
    ((__nv_bfloat162*)hi)[i * 2 + 1] = hh1;
    ((__nv_bfloat162*)lo)[i * 2]     = ll0;
    ((__nv_bfloat162*)lo)[i * 2 + 1] = ll1;
}

// ---------------------------------------------------------------------------
// Tensor-core GEMM: C[m,n] = sum_k A[m,k]*W[n,k] + bias[n]  (hi/lo bf16 inputs)
// 128x128 CTA tile, 8 warps (2M x 4N, warp tile 64x32), BK=32.
// SMEM tiles 128 rows x 32 bf16, row stride 40 bf16 (80B) -> ldmatrix
// conflict-free. 3-MMA compensated product: ah*bh + ah*bl + al*bh.
// mode 0: permuted write into g_q [b,head,s,d]; mode 1: row-major.
// ---------------------------------------------------------------------------
#define RSTRIDE 80   // bytes per smem row (40 bf16)

__global__ __launch_bounds__(256, 1) void gemm_mma_kernel(
    const __nv_bfloat16* __restrict__ Ah, const __nv_bfloat16* __restrict__ Al,
    const __nv_bfloat16* __restrict__ Wh, const __nv_bfloat16* __restrict__ Wl,
    const float* __restrict__ bias, float* __restrict__ C, int mode)
{
    __shared__ __align__(128) unsigned char sAh[128 * RSTRIDE];
    __shared__ __align__(128) unsigned char sAl[128 * RSTRIDE];
    __shared__ __align__(128) unsigned char sBh[128 * RSTRIDE];
    __shared__ __align__(128) unsigned char sBl[128 * RSTRIDE];

    const int tid  = threadIdx.x;
    const int wid  = tid >> 5;
    const int lane = tid & 31;
    const int n0 = blockIdx.x * 128;
    const int m0 = blockIdx.y * 128;
    const int wm = (wid >> 2) * 64;   // warp M offset
    const int wn = (wid & 3) * 32;    // warp N offset

    const uint32_t uAh = smem_u32(sAh), uAl = smem_u32(sAl);
    const uint32_t uBh = smem_u32(sBh), uBl = smem_u32(sBl);

    float acc[4][4][4];
#pragma unroll
    for (int i = 0; i < 4; i++)
#pragma unroll
        for (int j = 0; j < 4; j++)
#pragma unroll
            for (int r = 0; r < 4; r++) acc[i][j][r] = 0.0f;

    // global load coords: thread t loads rows (t>>2) and (t>>2)+64, 8 bf16 at col (t&3)*8
    const int lrow = tid >> 2;
    const int kce  = (tid & 3) * 8;          // element col
    const int kcb  = kce * 2;                // byte col

    const __nv_bfloat16* pAh = Ah + (size_t)(m0 + lrow) * H_ + kce;
    const __nv_bfloat16* pAl = Al + (size_t)(m0 + lrow) * H_ + kce;
    const __nv_bfloat16* pWh = Wh + (size_t)(n0 + lrow) * H_ + kce;
    const __nv_bfloat16* pWl = Wl + (size_t)(n0 + lrow) * H_ + kce;

    uint4 va[2], vb[2], vc[2], vd[2];
    // preload chunk 0
    va[0] = *(const uint4*)(pAh);            va[1] = *(const uint4*)(pAh + (size_t)64 * H_);
    vb[0] = *(const uint4*)(pAl);            vb[1] = *(const uint4*)(pAl + (size_t)64 * H_);
    vc[0] = *(const uint4*)(pWh);            vc[1] = *(const uint4*)(pWh + (size_t)64 * H_);
    vd[0] = *(const uint4*)(pWl);            vd[1] = *(const uint4*)(pWl + (size_t)64 * H_);

    // ldmatrix fragment addresses (fixed per thread, vary by tile/kstep)
    const int a_row = lane & 15;             // + wm + mf*16
    const int a_kb  = (lane >> 4) * 16;      // byte offset (8 bf16)
    const int b_row = (lane & 7) + ((lane >> 4) << 3);   // + wn + g*16
    const int b_kb  = ((lane >> 3) & 1) * 16;

    for (int kt = 0; kt < H_ / 32; kt++) {
        __syncthreads();
        {
            const uint32_t o0 = (uint32_t)lrow * RSTRIDE + kcb;
            const uint32_t o1 = (uint32_t)(lrow + 64) * RSTRIDE + kcb;
            *(uint4*)(sAh + o0) = va[0]; *(uint4*)(sAh + o1) = va[1];
            *(uint4*)(sAl + o0) = vb[0]; *(uint4*)(sAl + o1) = vb[1];
            *(uint4*)(sBh + o0) = vc[0]; *(uint4*)(sBh + o1) = vc[1];
            *(uint4*)(sBl + o0) = vd[0]; *(uint4*)(sBl + o1) = vd[1];
        }
        __syncthreads();

        if (kt < H_ / 32 - 1) {
            const size_t off = (size_t)(kt + 1) * 32;
            va[0] = *(const uint4*)(pAh + off); va[1] = *(const uint4*)(pAh + (size_t)64 * H_ + off);
            vb[0] = *(const uint4*)(pAl + off); vb[1] = *(const uint4*)(pAl + (size_t)64 * H_ + off);
            vc[0] = *(const uint4*)(pWh + off); vc[1] = *(const uint4*)(pWh + (size_t)64 * H_ + off);
            vd[0] = *(const uint4*)(pWl + off); vd[1] = *(const uint4*)(pWl + (size_t)64 * H_ + off);
        }

#pragma unroll
        for (int ks = 0; ks < 2; ks++) {
            const uint32_t kb = ks * 32;  // 16 bf16 = 32 bytes
            uint32_t ah[4][4], al[4][4], bh[2][4], bl[2][4];
#pragma unroll
            for (int mf = 0; mf < 4; mf++) {
                const uint32_t ro = (uint32_t)(wm + mf * 16 + a_row) * RSTRIDE + kb + a_kb;
                ldmat_x4(ah[mf], uAh + ro);
                ldmat_x4(al[mf], uAl + ro);
            }
#pragma unroll
            for (int g = 0; g < 2; g++) {
                const uint32_t ro = (uint32_t)(wn + g * 16 + b_row) * RSTRIDE + kb + b_kb;
                ldmat_x4(bh[g], uBh + ro);
                ldmat_x4(bl[g], uBl + ro);
            }
#pragma unroll
            for (int mf = 0; mf < 4; mf++)
#pragma unroll
                for (int g = 0; g < 2; g++)
#pragma unroll
                    for (int h = 0; h < 2; h++) {
                        float* c = acc[mf][g * 2 + h];
                        mma_bf16(c, ah[mf], &bh[g][h * 2]);
                        mma_bf16(c, ah[mf], &bl[g][h * 2]);
                        mma_bf16(c, al[mf], &bh[g][h * 2]);
                    }
        }
    }

    // epilogue: D[m][n] mapping: c0:(r, 2c) c1:(r, 2c+1) c2:(r+8, 2c) c3:(r+8, 2c+1)
    const int er = lane >> 2;
    const int ec = (lane & 3) * 2;
#pragma unroll
    for (int mf = 0; mf < 4; mf++)
#pragma unroll
        for (int nf = 0; nf < 4; nf++) {
            const float* c = acc[mf][nf];
#pragma unroll
            for (int r = 0; r < 4; r++) {
                const int m = m0 + wm + mf * 16 + er + ((r >> 1) << 3);
                const int n = n0 + wn + nf * 8 + ec + (r & 1);
                const float v = c[r] + bias[n];
                if (mode == 0) {
                    const int bb = m >> 11, s = m & 2047;
                    const int hh = n >> 7,  d = n & 127;
                    C[((size_t)(bb * NH_ + hh) * S_ + s) * D_ + d] = v;
                } else {
                    C[(size_t)m * H_ + n] = v;
                }
            }
        }
}

// ---------------------------------------------------------------------------
// Flash attention (fp32, causal, GQA) — unchanged (R4, passing).
// ---------------------------------------------------------------------------
#define QKV_STRIDE 130
#define P_STRIDE   65
#define ATT_SMEM_BYTES ((3 * 64 * QKV_STRIDE + 64 * P_STRIDE) * 4)

__global__ __launch_bounds__(256) void attn_kernel(
    const float* __restrict__ Q, const float* __restrict__ Kg,
    const float* __restrict__ Vg, float* __restrict__ ctx)
{
    extern __shared__ float sm[];
    float* Qs = sm;
    float* Ks = Qs + 64 * QKV_STRIDE;
    float* Vs = Ks + 64 * QKV_STRIDE;
    float* Ps = Vs + 64 * QKV_STRIDE;

    const int tid = threadIdx.x;
    const int tx = tid & 15;
    const int ty = tid >> 4;
    const int qt = blockIdx.x;
    const int hh = blockIdx.y;
    const int b  = blockIdx.z;
    const int kv = hh >> 2;
    const int q0 = qt * 64;

    const float* Qb = Q  + ((size_t)(b * NH_  + hh) * S_ + q0) * D_;
    const float* Kb = Kg + ((size_t)(b * NKV_ + kv) * S_) * D_;
    const float* Vb = Vg + ((size_t)(b * NKV_ + kv) * S_) * D_;

    const int fr = tid >> 5;
    const int fc = (tid & 31) * 4;

#pragma unroll
    for (int it = 0; it < 8; it++) {
        const int r = fr + it * 8;
        float4 v = *(const float4*)(Qb + (size_t)r * D_ + fc);
        float* dst = Qs + r * QKV_STRIDE + fc;
        dst[0] = v.x; dst[1] = v.y; dst[2] = v.z; dst[3] = v.w;
    }

    float m_i[4], l_i[4], o[4][8];
#pragma unroll
    for (int ii = 0; ii < 4; ii++) {
        m_i[ii] = -1e30f;
        l_i[ii] = 0.0f;
#pragma unroll
        for (int dd = 0; dd < 8; dd++) o[ii][dd] = 0.0f;
    }

    const float SCALE = 0.08838834764831845f;

    for (int kt = 0; kt <= qt; kt++) {
        const int k0 = kt * 64;
        __syncthreads();
#pragma unroll
        for (int it = 0; it < 8; it++) {
            const int r = fr + it * 8;
            float4 kvv = *(const float4*)(Kb + (size_t)(k0 + r) * D_ + fc);
            float4 vvv = *(const float4*)(Vb + (size_t)(k0 + r) * D_ + fc);
            float* kd = Ks + r * QKV_STRIDE + fc;
            float* vd = Vs + r * QKV_STRIDE + fc;
            kd[0] = kvv.x; kd[1] = kvv.y; kd[2] = kvv.z; kd[3] = kvv.w;
            vd[0] = vvv.x; vd[1] = vvv.y; vd[2] = vvv.z; vd[3] = vvv.w;
        }
        __syncthreads();

        float s[4][4];
#pragma unroll
        for (int ii = 0; ii < 4; ii++)
#pragma unroll
            for (int jj = 0; jj < 4; jj++) s[ii][jj] = 0.0f;

#pragma unroll 4
        for (int d = 0; d < 128; d++) {
            float qv[4], kvv[4];
#pragma unroll
            for (int ii = 0; ii < 4; ii++) qv[ii] = Qs[(ty + ii * 16) * QKV_STRIDE + d];
#pragma unroll
            for (int jj = 0; jj < 4; jj++) kvv[jj] = Ks[(tx + jj * 16) * QKV_STRIDE + d];
#pragma unroll
            for (int ii = 0; ii < 4; ii++)
#pragma unroll
                for (int jj = 0; jj < 4; jj++)
                    s[ii][jj] = fmaf(qv[ii], kvv[jj], s[ii][jj]);
        }

        const bool diag = (kt == qt);
#pragma unroll
        for (int ii = 0; ii < 4; ii++)
#pragma unroll
            for (int jj = 0; jj < 4; jj++) {
                s[ii][jj] *= SCALE;
                if (diag && (tx + jj * 16) > (ty + ii * 16)) s[ii][jj] = -1e30f;
            }

#pragma unroll
        for (int ii = 0; ii < 4; ii++) {
            float mx = fmaxf(fmaxf(s[ii][0], s[ii][1]), fmaxf(s[ii][2], s[ii][3]));
#pragma unroll
            for (int off = 1; off < 16; off <<= 1)
                mx = fmaxf(mx, __shfl_xor_sync(0xffffffffu, mx, off));
            const float mnew = fmaxf(m_i[ii], mx);
            const float corr = __expf(m_i[ii] - mnew);
            m_i[ii] = mnew;
            float ls = 0.0f;
#pragma unroll
            for (int jj = 0; jj < 4; jj++) {
                const float p = __expf(s[ii][jj] - mnew);
                s[ii][jj] = p;
                ls += p;
            }
#pragma unroll
            for (int off = 1; off < 16; off <<= 1)
                ls += __shfl_xor_sync(0xffffffffu, ls, off);
            l_i[ii] = l_i[ii] * corr + ls;
#pragma unroll
            for (int dd = 0; dd < 8; dd++) o[ii][dd] *= corr;
        }

#pragma unroll
        for (int ii = 0; ii < 4; ii++)
#pragma unroll
            for (int jj = 0; jj < 4; jj++)
                Ps[(ty + ii * 16) * P_STRIDE + tx + jj * 16] = s[ii][jj];
        __syncthreads();

#pragma unroll 4
        for (int j = 0; j < 64; j++) {
            float pv[4];
#pragma unroll
            for (int ii = 0; ii < 4; ii++) pv[ii] = Ps[(ty + ii * 16) * P_STRIDE + j];
#pragma unroll
            for (int dd = 0; dd < 8; dd++) {
                const float vvv = Vs[j * QKV_STRIDE + tx + dd * 16];
#pragma unroll
                for (int ii = 0; ii < 4; ii++)
                    o[ii][dd] = fmaf(pv[ii], vvv, o[ii][dd]);
            }
        }
    }

#pragma unroll
    for (int ii = 0; ii < 4; ii++) {
        const float inv = 1.0f / l_i[ii];
        const int qi = q0 + ty + ii * 16;
#pragma unroll
        for (int dd = 0; dd < 8; dd++) {
            ctx[((size_t)(b * S_ + qi)) * H_ + hh * D_ + tx + dd * 16] = o[ii][dd] * inv;
        }
    }
}

// ---------------------------------------------------------------------------
extern "C" void kernel_launch(void* const* d_in, const int* in_sizes, int n_in,
                              void* d_out, int out_size)
{
    const float* hidden = (const float*)d_in[0];
    const float* key    = (const float*)d_in[1];
    const float* value  = (const float*)d_in[2];
    const float* w_q    = (const float*)d_in[3];
    const float* b_q    = (const float*)d_in[4];
    const float* w_proj = (const float*)d_in[5];
    const float* b_proj = (const float*)d_in[6];
    float* out = (float*)d_out;

    float *qbuf = nullptr, *ctxbuf = nullptr;
    __nv_bfloat16 *aH = nullptr, *aL = nullptr, *wH = nullptr, *wL = nullptr;
    cudaGetSymbolAddress((void**)&qbuf, g_q);
    cudaGetSymbolAddress((void**)&ctxbuf, g_ctx);
    cudaGetSymbolAddress((void**)&aH, g_aH);
    cudaGetSymbolAddress((void**)&aL, g_aL);
    cudaGetSymbolAddress((void**)&wH, g_wH);
    cudaGetSymbolAddress((void**)&wL, g_wL);

    cudaFuncSetAttribute(attn_kernel, cudaFuncAttributeMaxDynamicSharedMemorySize, ATT_SMEM_BYTES);

    const int nAct4 = (B_ * S_ * H_) / 4;
    const int nW4   = (H_ * H_) / 4;

    dim3 ggrid(H_ / 128, (B_ * S_) / 128);  // (16, 32)

    // 1) Q projection -> g_q [b,head,s,d]
    split_bf16_kernel<<<(nAct4 + 255) / 256, 256>>>(hidden, aH, aL, nAct4);
    split_bf16_kernel<<<(nW4 + 255) / 256, 256>>>(w_q, wH, wL, nW4);
    gemm_mma_kernel<<<ggrid, 256>>>(aH, aL, wH, wL, b_q, qbuf, 0);

    // 2) causal GQA attention -> g_ctx [b,s,h]
    dim3 agrid(S_ / 64, NH_, B_);
    attn_kernel<<<agrid, 256, ATT_SMEM_BYTES>>>(qbuf, key, value, ctxbuf);

    // 3) output projection -> d_out
    split_bf16_kernel<<<(nAct4 + 255) / 256, 256>>>(ctxbuf, aH, aL, nAct4);
    split_bf16_kernel<<<(nW4 + 255) / 256, 256>>>(w_proj, wH, wL, nW4);
    gemm_mma_kernel<<<ggrid, 256>>>(aH, aL, wH, wL, b_proj, out, 1);
}

// round 10
// speedup vs baseline: 3.0251x; 3.0251x over previous
#include <cuda_runtime.h>
#include <cuda_bf16.h>
#include <cstdint>

// ---------------------------------------------------------------------------
// MultiLayerAttention: out = proj( softmax_causal( (hidden@Wq^T+bq) K^T / sqrt(D) ) V )
// B=2, S=2048, H=2048, 16 Q heads, 4 KV heads (G=4), D=128.
// R9 (resubmit): everything on tensor cores via mma.sync bf16 hi/lo split.
//     - GEMM: interleaved 3-pass MMA order (breaks acc dependency chains)
//     - Attention: 128x64 flash tiles, QK^T + PV on HMMA, fp32 online softmax
// ---------------------------------------------------------------------------

#define B_   2
#define S_   2048
#define H_   2048
#define NH_  16
#define NKV_ 4
#define D_   128

// Scratch (allocation-free rule: device globals), all bf16 hi/lo pairs
static __device__ __nv_bfloat16 g_aH[(size_t)B_ * S_ * H_];       // activations hi
static __device__ __nv_bfloat16 g_aL[(size_t)B_ * S_ * H_];       // activations lo
static __device__ __nv_bfloat16 g_wH[(size_t)H_ * H_];
static __device__ __nv_bfloat16 g_wL[(size_t)H_ * H_];
static __device__ __nv_bfloat16 g_qH[(size_t)B_ * NH_ * S_ * D_]; // [b,h,s,d]
static __device__ __nv_bfloat16 g_qL[(size_t)B_ * NH_ * S_ * D_];
static __device__ __nv_bfloat16 g_kH[(size_t)B_ * NKV_ * S_ * D_];// [b,kv,s,d]
static __device__ __nv_bfloat16 g_kL[(size_t)B_ * NKV_ * S_ * D_];
static __device__ __nv_bfloat16 g_vH[(size_t)B_ * NKV_ * D_ * S_];// [b,kv,d,s] (transposed!)
static __device__ __nv_bfloat16 g_vL[(size_t)B_ * NKV_ * D_ * S_];

// ============================ MMA helpers ==================================
__device__ __forceinline__ uint32_t smem_u32(const void* p) {
    uint32_t a;
    asm("{ .reg .u64 t; cvta.to.shared.u64 t, %1; cvt.u32.u64 %0, t; }" : "=r"(a) : "l"(p));
    return a;
}
__device__ __forceinline__ void ldmat_x4(uint32_t* r, uint32_t addr) {
    asm volatile("ldmatrix.sync.aligned.m8n8.x4.shared.b16 {%0,%1,%2,%3}, [%4];"
                 : "=r"(r[0]), "=r"(r[1]), "=r"(r[2]), "=r"(r[3]) : "r"(addr));
}
__device__ __forceinline__ void mma_bf16(float* d, const uint32_t* a, const uint32_t* b) {
    asm volatile("mma.sync.aligned.m16n8k16.row.col.f32.bf16.bf16.f32 "
                 "{%0,%1,%2,%3}, {%4,%5,%6,%7}, {%8,%9}, {%0,%1,%2,%3};"
                 : "+f"(d[0]), "+f"(d[1]), "+f"(d[2]), "+f"(d[3])
                 : "r"(a[0]), "r"(a[1]), "r"(a[2]), "r"(a[3]), "r"(b[0]), "r"(b[1]));
}
__device__ __forceinline__ uint32_t pack_bf16x2(float lo_val, float hi_val) {
    __nv_bfloat162 t{__float2bfloat16(lo_val), __float2bfloat16(hi_val)};
    return *reinterpret_cast<uint32_t*>(&t);
}

// ---------------------------------------------------------------------------
// fp32 -> (bf16 hi, bf16 lo) split (elementwise)
// ---------------------------------------------------------------------------
__global__ __launch_bounds__(256) void split_bf16_kernel(
    const float* __restrict__ src, __nv_bfloat16* __restrict__ hi,
    __nv_bfloat16* __restrict__ lo, int n4)
{
    int i = blockIdx.x * blockDim.x + threadIdx.x;
    if (i >= n4) return;
    float4 x = ((const float4*)src)[i];
    __nv_bfloat16 h0 = __float2bfloat16(x.x), h1 = __float2bfloat16(x.y);
    __nv_bfloat16 h2 = __float2bfloat16(x.z), h3 = __float2bfloat16(x.w);
    __nv_bfloat162 hh0{h0, h1}, hh1{h2, h3};
    __nv_bfloat162 ll0{__float2bfloat16(x.x - __bfloat162float(h0)),
                       __float2bfloat16(x.y - __bfloat162float(h1))};
    __nv_bfloat162 ll1{__float2bfloat16(x.z - __bfloat162float(h2)),
                       __float2bfloat16(x.w - __bfloat162float(h3))};
    ((__nv_bfloat162*)hi)[i * 2]     = hh0;
    ((__nv_bfloat162*)hi)[i * 2 + 1] = hh1;
    ((__nv_bfloat162*)lo)[i * 2]     = ll0;
    ((__nv_bfloat162*)lo)[i * 2 + 1] = ll1;
}

// ---------------------------------------------------------------------------
// V transpose + split: [bkv, s, d] fp32 -> [bkv, d, s] bf16 hi/lo
// ---------------------------------------------------------------------------
__global__ __launch_bounds__(256) void vsplit_t_kernel(
    const float* __restrict__ V, __nv_bfloat16* __restrict__ vh,
    __nv_bfloat16* __restrict__ vl)
{
    __shared__ float t[32][33];
    const int bkv = blockIdx.z;
    const int s0 = blockIdx.x * 32, d0 = blockIdx.y * 32;
    const int tx = threadIdx.x & 31, ty = threadIdx.x >> 5;  // ty 0..7
    const float* src = V + ((size_t)bkv * S_ + s0) * D_ + d0;
#pragma unroll
    for (int j = 0; j < 4; j++)
        t[ty + j * 8][tx] = src[(size_t)(ty + j * 8) * D_ + tx];
    __syncthreads();
#pragma unroll
    for (int j = 0; j < 4; j++) {
        const int dr = ty + j * 8;
        const float v = t[tx][dr];
        const __nv_bfloat16 h = __float2bfloat16(v);
        const size_t o = ((size_t)bkv * D_ + d0 + dr) * S_ + s0 + tx;
        vh[o] = h;
        vl[o] = __float2bfloat16(v - __bfloat162float(h));
    }
}

// ---------------------------------------------------------------------------
// Tensor-core GEMM: C[m,n] = sum_k A[m,k]*W[n,k] + bias[n]  (hi/lo bf16 inputs)
// 128x128 CTA tile, 8 warps (2M x 4N, warp tile 64x32), BK=32.
// 3-pass interleaved MMA order (acc reuse distance = 16 MMAs).
// mode 0: write bf16 hi/lo into g_q [b,head,s,d]; mode 1: fp32 row-major.
// ---------------------------------------------------------------------------
#define RSTRIDE 80   // bytes per smem row (40 bf16)

__global__ __launch_bounds__(256, 1) void gemm_mma_kernel(
    const __nv_bfloat16* __restrict__ Ah, const __nv_bfloat16* __restrict__ Al,
    const __nv_bfloat16* __restrict__ Wh, const __nv_bfloat16* __restrict__ Wl,
    const float* __restrict__ bias, float* __restrict__ C,
    __nv_bfloat16* __restrict__ CH, __nv_bfloat16* __restrict__ CL, int mode)
{
    __shared__ __align__(128) unsigned char sAh[128 * RSTRIDE];
    __shared__ __align__(128) unsigned char sAl[128 * RSTRIDE];
    __shared__ __align__(128) unsigned char sBh[128 * RSTRIDE];
    __shared__ __align__(128) unsigned char sBl[128 * RSTRIDE];

    const int tid  = threadIdx.x;
    const int wid  = tid >> 5;
    const int lane = tid & 31;
    const int n0 = blockIdx.x * 128;
    const int m0 = blockIdx.y * 128;
    const int wm = (wid >> 2) * 64;
    const int wn = (wid & 3) * 32;

    const uint32_t uAh = smem_u32(sAh), uAl = smem_u32(sAl);
    const uint32_t uBh = smem_u32(sBh), uBl = smem_u32(sBl);

    float acc[4][4][4];
#pragma unroll
    for (int i = 0; i < 4; i++)
#pragma unroll
        for (int j = 0; j < 4; j++)
#pragma unroll
            for (int r = 0; r < 4; r++) acc[i][j][r] = 0.0f;

    const int lrow = tid >> 2;
    const int kce  = (tid & 3) * 8;
    const int kcb  = kce * 2;

    const __nv_bfloat16* pAh = Ah + (size_t)(m0 + lrow) * H_ + kce;
    const __nv_bfloat16* pAl = Al + (size_t)(m0 + lrow) * H_ + kce;
    const __nv_bfloat16* pWh = Wh + (size_t)(n0 + lrow) * H_ + kce;
    const __nv_bfloat16* pWl = Wl + (size_t)(n0 + lrow) * H_ + kce;

    uint4 va[2], vb[2], vc[2], vd[2];
    va[0] = *(const uint4*)(pAh); va[1] = *(const uint4*)(pAh + (size_t)64 * H_);
    vb[0] = *(const uint4*)(pAl); vb[1] = *(const uint4*)(pAl + (size_t)64 * H_);
    vc[0] = *(const uint4*)(pWh); vc[1] = *(const uint4*)(pWh + (size_t)64 * H_);
    vd[0] = *(const uint4*)(pWl); vd[1] = *(const uint4*)(pWl + (size_t)64 * H_);

    const int a_row = lane & 15;
    const int a_kb  = (lane >> 4) * 16;
    const int b_row = (lane & 7) + ((lane >> 4) << 3);
    const int b_kb  = ((lane >> 3) & 1) * 16;

    for (int kt = 0; kt < H_ / 32; kt++) {
        __syncthreads();
        {
            const uint32_t o0 = (uint32_t)lrow * RSTRIDE + kcb;
            const uint32_t o1 = (uint32_t)(lrow + 64) * RSTRIDE + kcb;
            *(uint4*)(sAh + o0) = va[0]; *(uint4*)(sAh + o1) = va[1];
            *(uint4*)(sAl + o0) = vb[0]; *(uint4*)(sAl + o1) = vb[1];
            *(uint4*)(sBh + o0) = vc[0]; *(uint4*)(sBh + o1) = vc[1];
            *(uint4*)(sBl + o0) = vd[0]; *(uint4*)(sBl + o1) = vd[1];
        }
        __syncthreads();

        if (kt < H_ / 32 - 1) {
            const size_t off = (size_t)(kt + 1) * 32;
            va[0] = *(const uint4*)(pAh + off); va[1] = *(const uint4*)(pAh + (size_t)64 * H_ + off);
            vb[0] = *(const uint4*)(pAl + off); vb[1] = *(const uint4*)(pAl + (size_t)64 * H_ + off);
            vc[0] = *(const uint4*)(pWh + off); vc[1] = *(const uint4*)(pWh + (size_t)64 * H_ + off);
            vd[0] = *(const uint4*)(pWl + off); vd[1] = *(const uint4*)(pWl + (size_t)64 * H_ + off);
        }

#pragma unroll
        for (int ks = 0; ks < 2; ks++) {
            const uint32_t kb = ks * 32;
            uint32_t ah[4][4], al[4][4], bh[2][4], bl[2][4];
#pragma unroll
            for (int mf = 0; mf < 4; mf++) {
                const uint32_t ro = (uint32_t)(wm + mf * 16 + a_row) * RSTRIDE + kb + a_kb;
                ldmat_x4(ah[mf], uAh + ro);
                ldmat_x4(al[mf], uAl + ro);
            }
#pragma unroll
            for (int g = 0; g < 2; g++) {
                const uint32_t ro = (uint32_t)(wn + g * 16 + b_row) * RSTRIDE + kb + b_kb;
                ldmat_x4(bh[g], uBh + ro);
                ldmat_x4(bl[g], uBl + ro);
            }
            // 3 interleaved passes: acc reuse distance = 16 MMAs
#pragma unroll
            for (int mf = 0; mf < 4; mf++)
#pragma unroll
                for (int g = 0; g < 2; g++)
#pragma unroll
                    for (int h = 0; h < 2; h++)
                        mma_bf16(acc[mf][g * 2 + h], ah[mf], &bh[g][h * 2]);
#pragma unroll
            for (int mf = 0; mf < 4; mf++)
#pragma unroll
                for (int g = 0; g < 2; g++)
#pragma unroll
                    for (int h = 0; h < 2; h++)
                        mma_bf16(acc[mf][g * 2 + h], ah[mf], &bl[g][h * 2]);
#pragma unroll
            for (int mf = 0; mf < 4; mf++)
#pragma unroll
                for (int g = 0; g < 2; g++)
#pragma unroll
                    for (int h = 0; h < 2; h++)
                        mma_bf16(acc[mf][g * 2 + h], al[mf], &bh[g][h * 2]);
        }
    }

    const int er = lane >> 2;
    const int ec = (lane & 3) * 2;
#pragma unroll
    for (int mf = 0; mf < 4; mf++)
#pragma unroll
        for (int nf = 0; nf < 4; nf++) {
            const float* c = acc[mf][nf];
#pragma unroll
            for (int r = 0; r < 4; r++) {
                const int m = m0 + wm + mf * 16 + er + ((r >> 1) << 3);
                const int n = n0 + wn + nf * 8 + ec + (r & 1);
                const float v = c[r] + bias[n];
                if (mode == 0) {
                    const int bb = m >> 11, s = m & 2047;
                    const int hh = n >> 7,  d = n & 127;
                    const size_t o = ((size_t)(bb * NH_ + hh) * S_ + s) * D_ + d;
                    const __nv_bfloat16 h = __float2bfloat16(v);
                    CH[o] = h;
                    CL[o] = __float2bfloat16(v - __bfloat162float(h));
                } else {
                    C[(size_t)m * H_ + n] = v;
                }
            }
        }
}

// ---------------------------------------------------------------------------
// Flash attention on tensor cores. 128 q-rows per CTA, 64-k tiles, D=128.
// 8 warps x 16 q-rows. QK^T and PV via hi/lo-split mma.sync (3 MMAs each).
// Emits attention output directly as bf16 hi/lo into aH/aL [m][h].
// ---------------------------------------------------------------------------
#define STR_QK 272   // bytes per smem row for Q,K (128 bf16 + 8 pad)
#define STR_V  144   // bytes per smem row for V^T (64 bf16 + 8 pad)
#define OFF_QH 0
#define OFF_QL (128 * STR_QK)
#define OFF_KH (2 * 128 * STR_QK)
#define OFF_KL (2 * 128 * STR_QK + 64 * STR_QK)
#define OFF_VH (2 * 128 * STR_QK + 2 * 64 * STR_QK)
#define OFF_VL (2 * 128 * STR_QK + 2 * 64 * STR_QK + 128 * STR_V)
#define ATT_SMEM (2 * 128 * STR_QK + 2 * 64 * STR_QK + 2 * 128 * STR_V)

__global__ __launch_bounds__(256, 1) void attn_mma_kernel(
    const __nv_bfloat16* __restrict__ Qh, const __nv_bfloat16* __restrict__ Ql,
    const __nv_bfloat16* __restrict__ Kh, const __nv_bfloat16* __restrict__ Kl,
    const __nv_bfloat16* __restrict__ Vh, const __nv_bfloat16* __restrict__ Vl,
    __nv_bfloat16* __restrict__ outH, __nv_bfloat16* __restrict__ outL)
{
    extern __shared__ __align__(128) unsigned char smraw[];
    const uint32_t sb = smem_u32(smraw);
    const uint32_t uQh = sb + OFF_QH, uQl = sb + OFF_QL;
    const uint32_t uKh = sb + OFF_KH, uKl = sb + OFF_KL;
    const uint32_t uVh = sb + OFF_VH, uVl = sb + OFF_VL;

    const int tid = threadIdx.x;
    const int wid = tid >> 5;
    const int lane = tid & 31;
    const int bx = blockIdx.x;           // q tile (128 rows)
    const int head = blockIdx.y;
    const int b = blockIdx.z;
    const int kv = head >> 2;
    const int q0 = bx * 128;
    const int wm = wid * 16;

    // ---- load Q tile (once) ----
    {
        const __nv_bfloat16* qh = Qh + ((size_t)(b * NH_ + head) * S_ + q0) * D_;
        const __nv_bfloat16* ql = Ql + ((size_t)(b * NH_ + head) * S_ + q0) * D_;
        const int qc = tid & 15, qr = tid >> 4;
#pragma unroll
        for (int it = 0; it < 8; it++) {
            const int r = qr + it * 16;
            *(uint4*)(smraw + OFF_QH + r * STR_QK + qc * 16) = *(const uint4*)(qh + (size_t)r * D_ + qc * 8);
            *(uint4*)(smraw + OFF_QL + r * STR_QK + qc * 16) = *(const uint4*)(ql + (size_t)r * D_ + qc * 8);
        }
    }

    const __nv_bfloat16* kh = Kh + ((size_t)(b * NKV_ + kv) * S_) * D_;
    const __nv_bfloat16* kl = Kl + ((size_t)(b * NKV_ + kv) * S_) * D_;
    const __nv_bfloat16* vh = Vh + ((size_t)(b * NKV_ + kv) * D_) * S_;
    const __nv_bfloat16* vl = Vl + ((size_t)(b * NKV_ + kv) * D_) * S_;

    const int a_row = lane & 15;
    const int a_kb  = (lane >> 4) * 16;
    const int b_row = (lane & 7) + ((lane >> 4) << 3);
    const int b_kb  = ((lane >> 3) & 1) * 16;

    float m0v = -1e30f, m1v = -1e30f, l0v = 0.0f, l1v = 0.0f;
    float oacc[16][4];
#pragma unroll
    for (int i = 0; i < 16; i++)
#pragma unroll
        for (int r = 0; r < 4; r++) oacc[i][r] = 0.0f;

    const float SCALE = 0.08838834764831845f;  // 1/sqrt(128)
    const int n_kt = 2 * bx + 2;

    for (int kt = 0; kt < n_kt; kt++) {
        const int k0 = kt * 64;
        __syncthreads();
        // ---- load K (64x128, K-major) and V^T (128x64, d-major) tiles ----
        {
            const int kc = tid & 15, kr = tid >> 4;
#pragma unroll
            for (int it = 0; it < 4; it++) {
                const int r = kr + it * 16;
                *(uint4*)(smraw + OFF_KH + r * STR_QK + kc * 16) = *(const uint4*)(kh + (size_t)(k0 + r) * D_ + kc * 8);
                *(uint4*)(smraw + OFF_KL + r * STR_QK + kc * 16) = *(const uint4*)(kl + (size_t)(k0 + r) * D_ + kc * 8);
            }
            const int vc = tid & 7, vr = tid >> 3;
#pragma unroll
            for (int it = 0; it < 4; it++) {
                const int r = vr + it * 32;
                *(uint4*)(smraw + OFF_VH + r * STR_V + vc * 16) = *(const uint4*)(vh + (size_t)r * S_ + k0 + vc * 8);
                *(uint4*)(smraw + OFF_VL + r * STR_V + vc * 16) = *(const uint4*)(vl + (size_t)r * S_ + k0 + vc * 8);
            }
        }
        __syncthreads();

        if (k0 > q0 + wm + 15) continue;   // fully-masked warp tile

        // ---- S = Q K^T  (16 x 64 per warp) ----
        float sacc[8][4];
#pragma unroll
        for (int f = 0; f < 8; f++)
#pragma unroll
            for (int r = 0; r < 4; r++) sacc[f][r] = 0.0f;

#pragma unroll
        for (int dc = 0; dc < 8; dc++) {
            const uint32_t kb = dc * 32;
            uint32_t qa_h[4], qa_l[4];
            ldmat_x4(qa_h, uQh + (uint32_t)(wm + a_row) * STR_QK + kb + a_kb);
            ldmat_x4(qa_l, uQl + (uint32_t)(wm + a_row) * STR_QK + kb + a_kb);
            uint32_t kf_h[4][4], kf_l[4][4];
#pragma unroll
            for (int g = 0; g < 4; g++) {
                const uint32_t ro = (uint32_t)(g * 16 + b_row) * STR_QK + kb + b_kb;
                ldmat_x4(kf_h[g], uKh + ro);
                ldmat_x4(kf_l[g], uKl + ro);
            }
#pragma unroll
            for (int g = 0; g < 4; g++)
#pragma unroll
                for (int h = 0; h < 2; h++)
                    mma_bf16(sacc[g * 2 + h], qa_h, &kf_h[g][h * 2]);
#pragma unroll
            for (int g = 0; g < 4; g++)
#pragma unroll
                for (int h = 0; h < 2; h++)
                    mma_bf16(sacc[g * 2 + h], qa_h, &kf_l[g][h * 2]);
#pragma unroll
            for (int g = 0; g < 4; g++)
#pragma unroll
                for (int h = 0; h < 2; h++)
                    mma_bf16(sacc[g * 2 + h], qa_l, &kf_h[g][h * 2]);
        }

        // ---- scale + causal mask ----
        const int r0g = q0 + wm + (lane >> 2);  // global q row (half 0); half 1 = +8
#pragma unroll
        for (int f = 0; f < 8; f++) {
            const int kc = k0 + f * 8 + ((lane & 3) << 1);
            sacc[f][0] = (kc     <= r0g    ) ? sacc[f][0] * SCALE : -1e30f;
            sacc[f][1] = (kc + 1 <= r0g    ) ? sacc[f][1] * SCALE : -1e30f;
            sacc[f][2] = (kc     <= r0g + 8) ? sacc[f][2] * SCALE : -1e30f;
            sacc[f][3] = (kc + 1 <= r0g + 8) ? sacc[f][3] * SCALE : -1e30f;
        }

        // ---- online softmax ----
        float mx0 = -1e30f, mx1 = -1e30f;
#pragma unroll
        for (int f = 0; f < 8; f++) {
            mx0 = fmaxf(mx0, fmaxf(sacc[f][0], sacc[f][1]));
            mx1 = fmaxf(mx1, fmaxf(sacc[f][2], sacc[f][3]));
        }
        mx0 = fmaxf(mx0, __shfl_xor_sync(0xffffffffu, mx0, 1));
        mx0 = fmaxf(mx0, __shfl_xor_sync(0xffffffffu, mx0, 2));
        mx1 = fmaxf(mx1, __shfl_xor_sync(0xffffffffu, mx1, 1));
        mx1 = fmaxf(mx1, __shfl_xor_sync(0xffffffffu, mx1, 2));
        const float mn0 = fmaxf(m0v, mx0), mn1 = fmaxf(m1v, mx1);
        const float cr0 = __expf(m0v - mn0), cr1 = __expf(m1v - mn1);
        m0v = mn0; m1v = mn1;
        float ls0 = 0.0f, ls1 = 0.0f;
#pragma unroll
        for (int f = 0; f < 8; f++) {
            sacc[f][0] = __expf(sacc[f][0] - mn0);
            sacc[f][1] = __expf(sacc[f][1] - mn0);
            sacc[f][2] = __expf(sacc[f][2] - mn1);
            sacc[f][3] = __expf(sacc[f][3] - mn1);
            ls0 += sacc[f][0] + sacc[f][1];
            ls1 += sacc[f][2] + sacc[f][3];
        }
        ls0 += __shfl_xor_sync(0xffffffffu, ls0, 1);
        ls0 += __shfl_xor_sync(0xffffffffu, ls0, 2);
        ls1 += __shfl_xor_sync(0xffffffffu, ls1, 1);
        ls1 += __shfl_xor_sync(0xffffffffu, ls1, 2);
        l0v = l0v * cr0 + ls0;
        l1v = l1v * cr1 + ls1;
#pragma unroll
        for (int nf = 0; nf < 16; nf++) {
            oacc[nf][0] *= cr0; oacc[nf][1] *= cr0;
            oacc[nf][2] *= cr1; oacc[nf][3] *= cr1;
        }

        // ---- O += P V  (P from regs; V^T B-frags from smem) ----
#pragma unroll
        for (int c = 0; c < 4; c++) {
            uint32_t pa_h[4], pa_l[4];
            {
                const float* f0 = sacc[2 * c];
                const float* f1 = sacc[2 * c + 1];
                __nv_bfloat16 h00 = __float2bfloat16(f0[0]), h01 = __float2bfloat16(f0[1]);
                __nv_bfloat16 h02 = __float2bfloat16(f0[2]), h03 = __float2bfloat16(f0[3]);
                __nv_bfloat16 h10 = __float2bfloat16(f1[0]), h11 = __float2bfloat16(f1[1]);
                __nv_bfloat16 h12 = __float2bfloat16(f1[2]), h13 = __float2bfloat16(f1[3]);
                __nv_bfloat162 t;
                t = {h00, h01}; pa_h[0] = *(uint32_t*)&t;
                t = {h02, h03}; pa_h[1] = *(uint32_t*)&t;
                t = {h10, h11}; pa_h[2] = *(uint32_t*)&t;
                t = {h12, h13}; pa_h[3] = *(uint32_t*)&t;
                pa_l[0] = pack_bf16x2(f0[0] - __bfloat162float(h00), f0[1] - __bfloat162float(h01));
                pa_l[1] = pack_bf16x2(f0[2] - __bfloat162float(h02), f0[3] - __bfloat162float(h03));
                pa_l[2] = pack_bf16x2(f1[0] - __bfloat162float(h10), f1[1] - __bfloat162float(h11));
                pa_l[3] = pack_bf16x2(f1[2] - __bfloat162float(h12), f1[3] - __bfloat162float(h13));
            }
            const uint32_t kb = c * 32;
#pragma unroll
            for (int half = 0; half < 2; half++) {
                uint32_t vf_h[4][4], vf_l[4][4];
#pragma unroll
                for (int g = 0; g < 4; g++) {
                    const uint32_t ro = (uint32_t)(half * 64 + g * 16 + b_row) * STR_V + kb + b_kb;
                    ldmat_x4(vf_h[g], uVh + ro);
                    ldmat_x4(vf_l[g], uVl + ro);
                }
#pragma unroll
                for (int g = 0; g < 4; g++)
#pragma unroll
                    for (int h = 0; h < 2; h++)
                        mma_bf16(oacc[half * 8 + g * 2 + h], pa_h, &vf_h[g][h * 2]);
#pragma unroll
                for (int g = 0; g < 4; g++)
#pragma unroll
                    for (int h = 0; h < 2; h++)
                        mma_bf16(oacc[half * 8 + g * 2 + h], pa_h, &vf_l[g][h * 2]);
#pragma unroll
                for (int g = 0; g < 4; g++)
#pragma unroll
                    for (int h = 0; h < 2; h++)
                        mma_bf16(oacc[half * 8 + g * 2 + h], pa_l, &vf_h[g][h * 2]);
            }
        }
    }

    // ---- epilogue: normalize, split to bf16 hi/lo, write [m][head*128+d] ----
    const float inv0 = 1.0f / l0v, inv1 = 1.0f / l1v;
    const size_t m0g = (size_t)b * S_ + q0 + wm + (lane >> 2);
    const size_t m1g = m0g + 8;
    const int hc = head * 128 + ((lane & 3) << 1);
#pragma unroll
    for (int nf = 0; nf < 16; nf++) {
        const int d = nf * 8;
        const float v0 = oacc[nf][0] * inv0, v1 = oacc[nf][1] * inv0;
        const float v2 = oacc[nf][2] * inv1, v3 = oacc[nf][3] * inv1;
        const __nv_bfloat16 h0 = __float2bfloat16(v0), h1 = __float2bfloat16(v1);
        const __nv_bfloat16 h2 = __float2bfloat16(v2), h3 = __float2bfloat16(v3);
        __nv_bfloat162 t;
        t = {h0, h1}; *(__nv_bfloat162*)(outH + m0g * H_ + hc + d) = t;
        t = {h2, h3}; *(__nv_bfloat162*)(outH + m1g * H_ + hc + d) = t;
        t = {__float2bfloat16(v0 - __bfloat162float(h0)), __float2bfloat16(v1 - __bfloat162float(h1))};
        *(__nv_bfloat162*)(outL + m0g * H_ + hc + d) = t;
        t = {__float2bfloat16(v2 - __bfloat162float(h2)), __float2bfloat16(v3 - __bfloat162float(h3))};
        *(__nv_bfloat162*)(outL + m1g * H_ + hc + d) = t;
    }
}

// ---------------------------------------------------------------------------
extern "C" void kernel_launch(void* const* d_in, const int* in_sizes, int n_in,
                              void* d_out, int out_size)
{
    const float* hidden = (const float*)d_in[0];
    const float* key    = (const float*)d_in[1];
    const float* value  = (const float*)d_in[2];
    const float* w_q    = (const float*)d_in[3];
    const float* b_q    = (const float*)d_in[4];
    const float* w_proj = (const float*)d_in[5];
    const float* b_proj = (const float*)d_in[6];
    float* out = (float*)d_out;

    __nv_bfloat16 *aH, *aL, *wH, *wL, *qH, *qL, *kH, *kL, *vH, *vL;
    cudaGetSymbolAddress((void**)&aH, g_aH);
    cudaGetSymbolAddress((void**)&aL, g_aL);
    cudaGetSymbolAddress((void**)&wH, g_wH);
    cudaGetSymbolAddress((void**)&wL, g_wL);
    cudaGetSymbolAddress((void**)&qH, g_qH);
    cudaGetSymbolAddress((void**)&qL, g_qL);
    cudaGetSymbolAddress((void**)&kH, g_kH);
    cudaGetSymbolAddress((void**)&kL, g_kL);
    cudaGetSymbolAddress((void**)&vH, g_vH);
    cudaGetSymbolAddress((void**)&vL, g_vL);

    cudaFuncSetAttribute(attn_mma_kernel, cudaFuncAttributeMaxDynamicSharedMemorySize, ATT_SMEM);

    const int nAct4 = (B_ * S_ * H_) / 4;
    const int nW4   = (H_ * H_) / 4;
    const int nKV4  = (B_ * NKV_ * S_ * D_) / 4;

    dim3 ggrid(H_ / 128, (B_ * S_) / 128);  // (16, 32)

    // 1) Q projection (tensor cores), epilogue emits bf16 hi/lo [b,head,s,d]
    split_bf16_kernel<<<(nAct4 + 255) / 256, 256>>>(hidden, aH, aL, nAct4);
    split_bf16_kernel<<<(nW4 + 255) / 256, 256>>>(w_q, wH, wL, nW4);
    gemm_mma_kernel<<<ggrid, 256>>>(aH, aL, wH, wL, b_q, nullptr, qH, qL, 0);

    // 2) K split (plain) and V transpose-split
    split_bf16_kernel<<<(nKV4 + 255) / 256, 256>>>(key, kH, kL, nKV4);
    {
        dim3 vgrid(S_ / 32, D_ / 32, B_ * NKV_);
        vsplit_t_kernel<<<vgrid, 256>>>(value, vH, vL);
    }

    // 3) attention (tensor cores) -> aH/aL (bf16 hi/lo, [b*S+s][h])
    dim3 agrid(S_ / 128, NH_, B_);
    attn_mma_kernel<<<agrid, 256, ATT_SMEM>>>(qH, qL, kH, kL, vH, vL, aH, aL);

    // 4) output projection -> fp32 d_out
    split_bf16_kernel<<<(nW4 + 255) / 256, 256>>>(w_proj, wH, wL, nW4);
    gemm_mma_kernel<<<ggrid, 256>>>(aH, aL, wH, wL, b_proj, out, nullptr, nullptr, 1);
}